// round 1
// baseline (speedup 1.0000x reference)
#include <cuda_runtime.h>

// NonLocalAttention: B=4, C=256, H=W=64 -> N=4096, C8=32, C2=128
// Pipeline:
//   proj_kernel : theta[B,32,N], phi[B,32,N], g[B,N,128] = 1x1 convs of x
//   flash_kernel: online-softmax attention, att[B,N,128] (normalized PV)
//   out_kernel  : out = w_o @ att + b_o + x

#define B_ 4
#define C_ 256
#define N_ 4096
#define C8_ 32
#define C2_ 128

__device__ float d_theta[B_ * C8_ * N_];
__device__ float d_phi[B_ * C8_ * N_];
__device__ float d_g[(size_t)B_ * N_ * C2_];
__device__ float d_att[(size_t)B_ * N_ * C2_];

// ---- packed f32x2 helpers (sm_103a) ----
__device__ __forceinline__ unsigned long long pack2(float lo, float hi) {
    unsigned long long r;
    asm("mov.b64 %0, {%1, %2};" : "=l"(r) : "f"(lo), "f"(hi));
    return r;
}
__device__ __forceinline__ void fma2(unsigned long long& d, unsigned long long a,
                                     unsigned long long b) {
    asm("fma.rn.f32x2 %0, %1, %2, %0;" : "+l"(d) : "l"(a), "l"(b));
}
__device__ __forceinline__ void mul2(unsigned long long& d, unsigned long long a) {
    asm("mul.rn.f32x2 %0, %0, %1;" : "+l"(d) : "l"(a));
}
__device__ __forceinline__ float2 unpk(unsigned long long v) {
    float2 r;
    asm("mov.b64 {%0, %1}, %2;" : "=f"(r.x), "=f"(r.y) : "l"(v));
    return r;
}

// ============================================================================
// Kernel 1: projections. Block = 256 threads handles 64 pixels (all 192 outs).
// smem: ws[192][132] staged weights (per 128-c phase) + xst[64][132] x^T tile.
// ============================================================================
__global__ void __launch_bounds__(256) proj_kernel(
    const float* __restrict__ x,
    const float* __restrict__ wt, const float* __restrict__ bt,
    const float* __restrict__ wp, const float* __restrict__ bp,
    const float* __restrict__ wg, const float* __restrict__ bg) {
    extern __shared__ float sm[];
    float* ws  = sm;               // [192][132]
    float* xst = sm + 192 * 132;   // [64][132]

    const int b  = blockIdx.y;
    const int n0 = blockIdx.x * 64;
    const int tid = threadIdx.x;
    const int n  = tid & 63;
    const int og = tid >> 6;       // 0..3, each owns 48 output rows
    const int ob = og * 48;

    float acc[48];
#pragma unroll
    for (int j = 0; j < 48; j++) acc[j] = 0.f;

    for (int ph = 0; ph < 2; ph++) {
        __syncthreads();
        // stage weights [192][128] for this c-phase (float4 coalesced)
        for (int it = 0; it < 24; it++) {
            int idx = it * 256 + tid;       // 0..6143
            int o   = idx >> 5;
            int c4  = idx & 31;
            const float* src;
            if (o < 32)       src = wt + o * C_;
            else if (o < 64)  src = wp + (o - 32) * C_;
            else              src = wg + (o - 64) * C_;
            *(float4*)(ws + o * 132 + c4 * 4) =
                *(const float4*)(src + ph * 128 + c4 * 4);
        }
        // stage x transposed: xst[n][c] = x[b][ph*128+c][n0+n]
        for (int it = 0; it < 32; it++) {
            int idx = it * 256 + tid;
            int c   = idx >> 6;
            int nn  = idx & 63;
            xst[nn * 132 + c] =
                x[((size_t)b * C_ + ph * 128 + c) * N_ + n0 + nn];
        }
        __syncthreads();

        for (int c4 = 0; c4 < 32; c4++) {
            float4 xv = *(const float4*)(xst + n * 132 + c4 * 4);
#pragma unroll
            for (int j = 0; j < 48; j++) {
                float4 wv = *(const float4*)(ws + (ob + j) * 132 + c4 * 4);
                acc[j] += wv.x * xv.x + wv.y * xv.y + wv.z * xv.z + wv.w * xv.w;
            }
        }
    }

    // write with bias
#pragma unroll
    for (int j = 0; j < 48; j++) {
        int o = ob + j;
        if (o < 32) {
            d_theta[((size_t)b * C8_ + o) * N_ + n0 + n] = acc[j] + bt[o];
        } else if (o < 64) {
            d_phi[((size_t)b * C8_ + (o - 32)) * N_ + n0 + n] = acc[j] + bp[o - 32];
        } else {
            d_g[((size_t)b * N_ + n0 + n) * C2_ + (o - 64)] = acc[j] + bg[o - 64];
        }
    }
}

// ============================================================================
// Kernel 2: flash attention. Block = 256 threads (16x16), 64 queries.
// Per key tile (64): S = theta^T phi (K=32), online softmax, O += P g^T
// (PV in packed f32x2). att output is normalized.
// ============================================================================
__global__ void __launch_bounds__(256, 2) flash_kernel() {
    extern __shared__ float sm[];
    float* th_s = sm;                 // [32][64]
    float* ph_s = sm + 2048;          // [32][64]
    float* g_s  = sm + 4096;          // [64][132]
    float* p_s  = sm + 4096 + 8448;   // [64][68]  (P^T: [k][q])

    const int b  = blockIdx.y;
    const int q0 = blockIdx.x * 64;
    const int tid = threadIdx.x;
    const int tx = tid & 15;          // key / c2 group
    const int ty = tid >> 4;          // query group

    // load theta tile once
    for (int idx = tid; idx < 2048; idx += 256) {
        int c = idx >> 6, q = idx & 63;
        th_s[c * 64 + q] = d_theta[((size_t)b * C8_ + c) * N_ + q0 + q];
    }

    float m_i[4], l_i[4];
    unsigned long long acc[4][4];     // [q][c2 pair], c2 = tx*8 + 2j
#pragma unroll
    for (int i = 0; i < 4; i++) {
        m_i[i] = -1e30f;
        l_i[i] = 0.f;
#pragma unroll
        for (int j = 0; j < 4; j++) acc[i][j] = 0ULL;
    }

    for (int kt = 0; kt < N_; kt += 64) {
        __syncthreads();
        // load phi tile [32][64]
        for (int idx = tid; idx < 2048; idx += 256) {
            int c = idx >> 6, k = idx & 63;
            ph_s[c * 64 + k] = d_phi[((size_t)b * C8_ + c) * N_ + kt + k];
        }
        // load g tile [64][128] (float4 coalesced, conflict-free STS)
        {
            const float4* gg = (const float4*)(d_g + ((size_t)b * N_ + kt) * C2_);
            int c4 = tid & 31;
            int kb = tid >> 5;
#pragma unroll
            for (int r = 0; r < 8; r++) {
                int k = r * 8 + kb;
                *(float4*)(g_s + k * 132 + c4 * 4) = gg[k * 32 + c4];
            }
        }
        __syncthreads();

        // ---- GEMM1: S[4q][4k] = sum_c theta * phi ----
        float s[4][4];
#pragma unroll
        for (int i = 0; i < 4; i++)
#pragma unroll
            for (int j = 0; j < 4; j++) s[i][j] = 0.f;

#pragma unroll
        for (int c = 0; c < 32; c++) {
            float4 a4 = *(const float4*)(th_s + c * 64 + ty * 4);
            float4 b4 = *(const float4*)(ph_s + c * 64 + tx * 4);
            float av[4] = {a4.x, a4.y, a4.z, a4.w};
            float bv[4] = {b4.x, b4.y, b4.z, b4.w};
#pragma unroll
            for (int i = 0; i < 4; i++)
#pragma unroll
                for (int j = 0; j < 4; j++) s[i][j] += av[i] * bv[j];
        }

        // ---- online softmax per query row (16 lanes own a row) ----
#pragma unroll
        for (int i = 0; i < 4; i++) {
            float rm = fmaxf(fmaxf(s[i][0], s[i][1]), fmaxf(s[i][2], s[i][3]));
            rm = fmaxf(rm, __shfl_xor_sync(0xffffffffu, rm, 1, 16));
            rm = fmaxf(rm, __shfl_xor_sync(0xffffffffu, rm, 2, 16));
            rm = fmaxf(rm, __shfl_xor_sync(0xffffffffu, rm, 4, 16));
            rm = fmaxf(rm, __shfl_xor_sync(0xffffffffu, rm, 8, 16));
            float mnew = fmaxf(m_i[i], rm);
            float corr = __expf(m_i[i] - mnew);
            float rs = 0.f;
#pragma unroll
            for (int j = 0; j < 4; j++) {
                s[i][j] = __expf(s[i][j] - mnew);
                rs += s[i][j];
            }
            rs += __shfl_xor_sync(0xffffffffu, rs, 1, 16);
            rs += __shfl_xor_sync(0xffffffffu, rs, 2, 16);
            rs += __shfl_xor_sync(0xffffffffu, rs, 4, 16);
            rs += __shfl_xor_sync(0xffffffffu, rs, 8, 16);
            l_i[i] = l_i[i] * corr + rs;
            m_i[i] = mnew;
            unsigned long long cc = pack2(corr, corr);
#pragma unroll
            for (int j = 0; j < 4; j++) mul2(acc[i][j], cc);
        }

        // write P^T[k][q] (float4 over q)
#pragma unroll
        for (int j = 0; j < 4; j++) {
            float4 v = make_float4(s[0][j], s[1][j], s[2][j], s[3][j]);
            *(float4*)(p_s + (tx * 4 + j) * 68 + ty * 4) = v;
        }
        __syncthreads();

        // ---- GEMM2: acc[q][c2] += sum_k P[q][k] * g[k][c2]  (f32x2) ----
#pragma unroll 4
        for (int k = 0; k < 64; k++) {
            float4 pv = *(const float4*)(p_s + k * 68 + ty * 4);
            const unsigned long long* grow =
                (const unsigned long long*)(g_s + k * 132 + tx * 8);
            unsigned long long g0 = grow[0], g1 = grow[1];
            unsigned long long g2 = grow[2], g3 = grow[3];
            float pvv[4] = {pv.x, pv.y, pv.z, pv.w};
#pragma unroll
            for (int i = 0; i < 4; i++) {
                unsigned long long pp = pack2(pvv[i], pvv[i]);
                fma2(acc[i][0], pp, g0);
                fma2(acc[i][1], pp, g1);
                fma2(acc[i][2], pp, g2);
                fma2(acc[i][3], pp, g3);
            }
        }
    }

    // normalize + store att[b][q][c2]
#pragma unroll
    for (int i = 0; i < 4; i++) {
        float inv = 1.0f / l_i[i];
        float* dst = d_att + ((size_t)b * N_ + q0 + ty * 4 + i) * C2_ + tx * 8;
        float2 v0 = unpk(acc[i][0]), v1 = unpk(acc[i][1]);
        float2 v2 = unpk(acc[i][2]), v3 = unpk(acc[i][3]);
        *(float4*)dst = make_float4(v0.x * inv, v0.y * inv, v1.x * inv, v1.y * inv);
        *(float4*)(dst + 4) =
            make_float4(v2.x * inv, v2.y * inv, v3.x * inv, v3.y * inv);
    }
}

// ============================================================================
// Kernel 3: out = w_o @ att + b_o + x   (residual), [B][C][N] output.
// Block = 256 threads handles 64 pixels x all 256 channels, phased over c2.
// ============================================================================
__global__ void __launch_bounds__(256) out_kernel(
    const float* __restrict__ wo, const float* __restrict__ bo,
    const float* __restrict__ x, float* __restrict__ out) {
    extern __shared__ float sm[];
    float* wo_s = sm;              // [256][68]
    float* at_s = sm + 256 * 68;   // [64][68]

    const int b  = blockIdx.y;
    const int n0 = blockIdx.x * 64;
    const int tid = threadIdx.x;
    const int n  = tid & 63;
    const int cg = tid >> 6;       // 0..3, each owns 64 channels
    const int cb = cg * 64;

    float acc[64];
#pragma unroll
    for (int j = 0; j < 64; j++) acc[j] = 0.f;

    for (int ph = 0; ph < 2; ph++) {
        __syncthreads();
        // stage w_o [256][64] for this c2-phase
        for (int it = 0; it < 16; it++) {
            int idx = it * 256 + tid;   // 0..4095
            int c = idx >> 4, c4 = idx & 15;
            *(float4*)(wo_s + c * 68 + c4 * 4) =
                *(const float4*)(wo + c * C2_ + ph * 64 + c4 * 4);
        }
        // stage att [64][64]
        for (int it = 0; it < 4; it++) {
            int idx = it * 256 + tid;   // 0..1023
            int r = idx >> 4, c4 = idx & 15;
            *(float4*)(at_s + r * 68 + c4 * 4) =
                *(const float4*)(d_att + ((size_t)b * N_ + n0 + r) * C2_ +
                                 ph * 64 + c4 * 4);
        }
        __syncthreads();

        for (int c4 = 0; c4 < 16; c4++) {
            float4 av = *(const float4*)(at_s + n * 68 + c4 * 4);
#pragma unroll
            for (int j = 0; j < 64; j++) {
                float4 wv = *(const float4*)(wo_s + (cb + j) * 68 + c4 * 4);
                acc[j] += wv.x * av.x + wv.y * av.y + wv.z * av.z + wv.w * av.w;
            }
        }
    }

#pragma unroll
    for (int j = 0; j < 64; j++) {
        int c = cb + j;
        size_t idx = ((size_t)b * C_ + c) * N_ + n0 + n;
        out[idx] = acc[j] + bo[c] + x[idx];
    }
}

// ============================================================================
extern "C" void kernel_launch(void* const* d_in, const int* in_sizes, int n_in,
                              void* d_out, int out_size) {
    (void)in_sizes; (void)n_in; (void)out_size;
    const float* x  = (const float*)d_in[0];
    const float* wt = (const float*)d_in[1];
    const float* bt = (const float*)d_in[2];
    const float* wp = (const float*)d_in[3];
    const float* bp = (const float*)d_in[4];
    const float* wg = (const float*)d_in[5];
    const float* bg = (const float*)d_in[6];
    const float* wo = (const float*)d_in[7];
    const float* bo = (const float*)d_in[8];
    float* out = (float*)d_out;

    const int smem_proj  = (192 * 132 + 64 * 132) * 4;   // 135168
    const int smem_flash = (2048 + 2048 + 64 * 132 + 64 * 68) * 4;  // 67584
    const int smem_out   = (256 * 68 + 64 * 68) * 4;     // 87040

    cudaFuncSetAttribute(proj_kernel,
                         cudaFuncAttributeMaxDynamicSharedMemorySize, smem_proj);
    cudaFuncSetAttribute(flash_kernel,
                         cudaFuncAttributeMaxDynamicSharedMemorySize, smem_flash);
    cudaFuncSetAttribute(out_kernel,
                         cudaFuncAttributeMaxDynamicSharedMemorySize, smem_out);

    dim3 grid(N_ / 64, B_);
    proj_kernel<<<grid, 256, smem_proj>>>(x, wt, bt, wp, bp, wg, bg);
    flash_kernel<<<grid, 256, smem_flash>>>();
    out_kernel<<<grid, 256, smem_out>>>(wo, bo, x, out);
}

// round 2
// speedup vs baseline: 2.8468x; 2.8468x over previous
#include <cuda_runtime.h>

// NonLocalAttention: B=4, C=256, H=W=64 -> N=4096, C8=32, C2=128
//   proj_kernel    : theta/phi/g projections (fp32, unchanged from R1)
//   flash_tc_kernel: tf32 mma.sync flash attention, unnormalized exp softmax
//   out_kernel     : w_o @ att + b_o + x (unchanged from R1)

#define B_ 4
#define C_ 256
#define N_ 4096
#define C8_ 32
#define C2_ 128

__device__ float d_theta[B_ * C8_ * N_];
__device__ float d_phi[B_ * C8_ * N_];
__device__ float d_g[(size_t)B_ * N_ * C2_];
__device__ float d_att[(size_t)B_ * N_ * C2_];

// ---- intrinsics ----
__device__ __forceinline__ unsigned cvt_tf32(float x) {
    unsigned r;
    asm("cvt.rna.tf32.f32 %0, %1;" : "=r"(r) : "f"(x));
    return r;
}
__device__ __forceinline__ float ex2f(float x) {
    float r;
    asm("ex2.approx.f32 %0, %1;" : "=f"(r) : "f"(x));
    return r;
}
__device__ __forceinline__ void mma_tf32(
    float& c0, float& c1, float& c2, float& c3,
    unsigned a0, unsigned a1, unsigned a2, unsigned a3,
    unsigned b0, unsigned b1) {
    asm("mma.sync.aligned.m16n8k8.row.col.f32.tf32.tf32.f32 "
        "{%0,%1,%2,%3}, {%4,%5,%6,%7}, {%8,%9}, {%0,%1,%2,%3};"
        : "+f"(c0), "+f"(c1), "+f"(c2), "+f"(c3)
        : "r"(a0), "r"(a1), "r"(a2), "r"(a3), "r"(b0), "r"(b1));
}

// ============================================================================
// Kernel 1: projections (unchanged from R1)
// ============================================================================
__global__ void __launch_bounds__(256) proj_kernel(
    const float* __restrict__ x,
    const float* __restrict__ wt, const float* __restrict__ bt,
    const float* __restrict__ wp, const float* __restrict__ bp,
    const float* __restrict__ wg, const float* __restrict__ bg) {
    extern __shared__ float sm[];
    float* ws  = sm;               // [192][132]
    float* xst = sm + 192 * 132;   // [64][132]

    const int b  = blockIdx.y;
    const int n0 = blockIdx.x * 64;
    const int tid = threadIdx.x;
    const int n  = tid & 63;
    const int og = tid >> 6;
    const int ob = og * 48;

    float acc[48];
#pragma unroll
    for (int j = 0; j < 48; j++) acc[j] = 0.f;

    for (int ph = 0; ph < 2; ph++) {
        __syncthreads();
        for (int it = 0; it < 24; it++) {
            int idx = it * 256 + tid;
            int o   = idx >> 5;
            int c4  = idx & 31;
            const float* src;
            if (o < 32)       src = wt + o * C_;
            else if (o < 64)  src = wp + (o - 32) * C_;
            else              src = wg + (o - 64) * C_;
            *(float4*)(ws + o * 132 + c4 * 4) =
                *(const float4*)(src + ph * 128 + c4 * 4);
        }
        for (int it = 0; it < 32; it++) {
            int idx = it * 256 + tid;
            int c   = idx >> 6;
            int nn  = idx & 63;
            xst[nn * 132 + c] =
                x[((size_t)b * C_ + ph * 128 + c) * N_ + n0 + nn];
        }
        __syncthreads();

        for (int c4 = 0; c4 < 32; c4++) {
            float4 xv = *(const float4*)(xst + n * 132 + c4 * 4);
#pragma unroll
            for (int j = 0; j < 48; j++) {
                float4 wv = *(const float4*)(ws + (ob + j) * 132 + c4 * 4);
                acc[j] += wv.x * xv.x + wv.y * xv.y + wv.z * xv.z + wv.w * xv.w;
            }
        }
    }

#pragma unroll
    for (int j = 0; j < 48; j++) {
        int o = ob + j;
        if (o < 32) {
            d_theta[((size_t)b * C8_ + o) * N_ + n0 + n] = acc[j] + bt[o];
        } else if (o < 64) {
            d_phi[((size_t)b * C8_ + (o - 32)) * N_ + n0 + n] = acc[j] + bp[o - 32];
        } else {
            d_g[((size_t)b * N_ + n0 + n) * C2_ + (o - 64)] = acc[j] + bg[o - 64];
        }
    }
}

// ============================================================================
// Kernel 2: tf32 tensor-core flash attention.
// CTA = 128 threads (4 warps), q-tile = 64 (16 rows/warp), key-tile = 64.
// Unnormalized softmax: P = exp2(S * log2e_prefolded), l = rowsum, O/l at end.
// ============================================================================
__global__ void __launch_bounds__(128, 2) flash_tc_kernel() {
    extern __shared__ float sm[];
    float* phi_s = sm;              // [64][36]  phi[k][c]
    float* g_s   = sm + 64 * 36;    // [64][136] g[k][c2]

    const int b   = blockIdx.y;
    const int q0  = blockIdx.x * 64;
    const int tid = threadIdx.x;
    const int w    = tid >> 5;
    const int lane = tid & 31;
    const int qr = lane >> 2;   // row-in-group 0..7
    const int qc = lane & 3;    // col-in-group 0..3
    const int row0 = q0 + w * 16 + qr;

    // theta A-fragments (held all iterations), log2(e) folded in
    const float LOG2E = 1.4426950408889634f;
    unsigned at[4][4];
    {
        const float* tp = d_theta + (size_t)b * C8_ * N_;
#pragma unroll
        for (int kc = 0; kc < 4; kc++) {
            int c = kc * 8 + qc;
            at[kc][0] = cvt_tf32(tp[(size_t)c * N_ + row0] * LOG2E);
            at[kc][1] = cvt_tf32(tp[(size_t)c * N_ + row0 + 8] * LOG2E);
            at[kc][2] = cvt_tf32(tp[(size_t)(c + 4) * N_ + row0] * LOG2E);
            at[kc][3] = cvt_tf32(tp[(size_t)(c + 4) * N_ + row0 + 8] * LOG2E);
        }
    }

    float O[16][4];
#pragma unroll
    for (int nt = 0; nt < 16; nt++)
#pragma unroll
        for (int j = 0; j < 4; j++) O[nt][j] = 0.f;
    float l0 = 0.f, l1 = 0.f;

    const int srcA = (lane & ~3) | ((lane & 3) >> 1);
    const int srcB = srcA + 2;
    const bool odd = lane & 1;

    for (int kt = 0; kt < N_; kt += 64) {
        __syncthreads();
        // stage phi tile: phi_s[k][c] = phi[b][c][kt+k]
#pragma unroll
        for (int it = 0; it < 16; it++) {
            int idx = it * 128 + tid;
            int c = idx >> 6, k = idx & 63;
            phi_s[k * 36 + c] = d_phi[((size_t)b * C8_ + c) * N_ + kt + k];
        }
        // stage g tile: g_s[k][c2] (coalesced float4)
        {
            const float4* gg = (const float4*)(d_g + ((size_t)b * N_ + kt) * C2_);
#pragma unroll
            for (int it = 0; it < 16; it++) {
                int idx = it * 128 + tid;
                int k = idx >> 5, c4 = idx & 31;
                *(float4*)(g_s + k * 136 + c4 * 4) = gg[idx];
            }
        }
        __syncthreads();

        // ---- GEMM1: S[16q x 64k] = theta x phi^T ----
        float s[8][4];
#pragma unroll
        for (int nt = 0; nt < 8; nt++)
#pragma unroll
            for (int j = 0; j < 4; j++) s[nt][j] = 0.f;

#pragma unroll
        for (int kc = 0; kc < 4; kc++) {
            const float* pb = phi_s + qr * 36 + kc * 8 + qc;
#pragma unroll
            for (int nt = 0; nt < 8; nt++) {
                unsigned b0 = __float_as_uint(pb[nt * 8 * 36]);
                unsigned b1 = __float_as_uint(pb[nt * 8 * 36 + 4]);
                mma_tf32(s[nt][0], s[nt][1], s[nt][2], s[nt][3],
                         at[kc][0], at[kc][1], at[kc][2], at[kc][3], b0, b1);
            }
        }

        // ---- exp2 + row-sum accumulation (unnormalized) ----
        unsigned p[8][4];
#pragma unroll
        for (int nt = 0; nt < 8; nt++) {
            float e0 = ex2f(s[nt][0]);
            float e1 = ex2f(s[nt][1]);
            float e2 = ex2f(s[nt][2]);
            float e3 = ex2f(s[nt][3]);
            l0 += e0 + e1;
            l1 += e2 + e3;
            p[nt][0] = __float_as_uint(e0);
            p[nt][1] = __float_as_uint(e1);
            p[nt][2] = __float_as_uint(e2);
            p[nt][3] = __float_as_uint(e3);
        }

        // ---- GEMM2: O[16q x 128c2] += P x g ----
#pragma unroll
        for (int ks = 0; ks < 8; ks++) {
            unsigned v00 = __shfl_sync(0xffffffffu, p[ks][0], srcA);
            unsigned v01 = __shfl_sync(0xffffffffu, p[ks][1], srcA);
            unsigned v10 = __shfl_sync(0xffffffffu, p[ks][2], srcA);
            unsigned v11 = __shfl_sync(0xffffffffu, p[ks][3], srcA);
            unsigned u00 = __shfl_sync(0xffffffffu, p[ks][0], srcB);
            unsigned u01 = __shfl_sync(0xffffffffu, p[ks][1], srcB);
            unsigned u10 = __shfl_sync(0xffffffffu, p[ks][2], srcB);
            unsigned u11 = __shfl_sync(0xffffffffu, p[ks][3], srcB);
            unsigned a0 = odd ? v01 : v00;
            unsigned a1 = odd ? v11 : v10;
            unsigned a2 = odd ? u01 : u00;
            unsigned a3 = odd ? u11 : u10;

            const float* gb = g_s + (ks * 8 + qc) * 136 + qr;
#pragma unroll
            for (int nt = 0; nt < 16; nt++) {
                unsigned b0 = __float_as_uint(gb[nt * 8]);
                unsigned b1 = __float_as_uint(gb[nt * 8 + 4 * 136]);
                mma_tf32(O[nt][0], O[nt][1], O[nt][2], O[nt][3],
                         a0, a1, a2, a3, b0, b1);
            }
        }
    }

    // finalize: reduce l within quads, normalize, store
    l0 += __shfl_xor_sync(0xffffffffu, l0, 1);
    l0 += __shfl_xor_sync(0xffffffffu, l0, 2);
    l1 += __shfl_xor_sync(0xffffffffu, l1, 1);
    l1 += __shfl_xor_sync(0xffffffffu, l1, 2);
    float inv0 = 1.0f / l0;
    float inv1 = 1.0f / l1;

    float* dst0 = d_att + ((size_t)b * N_ + row0) * C2_ + qc * 2;
#pragma unroll
    for (int nt = 0; nt < 16; nt++) {
        *(float2*)(dst0 + nt * 8) =
            make_float2(O[nt][0] * inv0, O[nt][1] * inv0);
        *(float2*)(dst0 + 8 * C2_ + nt * 8) =
            make_float2(O[nt][2] * inv1, O[nt][3] * inv1);
    }
}

// ============================================================================
// Kernel 3: out = w_o @ att + b_o + x (unchanged from R1)
// ============================================================================
__global__ void __launch_bounds__(256) out_kernel(
    const float* __restrict__ wo, const float* __restrict__ bo,
    const float* __restrict__ x, float* __restrict__ out) {
    extern __shared__ float sm[];
    float* wo_s = sm;              // [256][68]
    float* at_s = sm + 256 * 68;   // [64][68]

    const int b  = blockIdx.y;
    const int n0 = blockIdx.x * 64;
    const int tid = threadIdx.x;
    const int n  = tid & 63;
    const int cg = tid >> 6;
    const int cb = cg * 64;

    float acc[64];
#pragma unroll
    for (int j = 0; j < 64; j++) acc[j] = 0.f;

    for (int ph = 0; ph < 2; ph++) {
        __syncthreads();
        for (int it = 0; it < 16; it++) {
            int idx = it * 256 + tid;
            int c = idx >> 4, c4 = idx & 15;
            *(float4*)(wo_s + c * 68 + c4 * 4) =
                *(const float4*)(wo + c * C2_ + ph * 64 + c4 * 4);
        }
        for (int it = 0; it < 4; it++) {
            int idx = it * 256 + tid;
            int r = idx >> 4, c4 = idx & 15;
            *(float4*)(at_s + r * 68 + c4 * 4) =
                *(const float4*)(d_att + ((size_t)b * N_ + n0 + r) * C2_ +
                                 ph * 64 + c4 * 4);
        }
        __syncthreads();

        for (int c4 = 0; c4 < 16; c4++) {
            float4 av = *(const float4*)(at_s + n * 68 + c4 * 4);
#pragma unroll
            for (int j = 0; j < 64; j++) {
                float4 wv = *(const float4*)(wo_s + (cb + j) * 68 + c4 * 4);
                acc[j] += wv.x * av.x + wv.y * av.y + wv.z * av.z + wv.w * av.w;
            }
        }
    }

#pragma unroll
    for (int j = 0; j < 64; j++) {
        int c = cb + j;
        size_t idx = ((size_t)b * C_ + c) * N_ + n0 + n;
        out[idx] = acc[j] + bo[c] + x[idx];
    }
}

// ============================================================================
extern "C" void kernel_launch(void* const* d_in, const int* in_sizes, int n_in,
                              void* d_out, int out_size) {
    (void)in_sizes; (void)n_in; (void)out_size;
    const float* x  = (const float*)d_in[0];
    const float* wt = (const float*)d_in[1];
    const float* bt = (const float*)d_in[2];
    const float* wp = (const float*)d_in[3];
    const float* bp = (const float*)d_in[4];
    const float* wg = (const float*)d_in[5];
    const float* bg = (const float*)d_in[6];
    const float* wo = (const float*)d_in[7];
    const float* bo = (const float*)d_in[8];
    float* out = (float*)d_out;

    const int smem_proj  = (192 * 132 + 64 * 132) * 4;
    const int smem_flash = (64 * 36 + 64 * 136) * 4;   // 44032
    const int smem_out   = (256 * 68 + 64 * 68) * 4;

    cudaFuncSetAttribute(proj_kernel,
                         cudaFuncAttributeMaxDynamicSharedMemorySize, smem_proj);
    cudaFuncSetAttribute(flash_tc_kernel,
                         cudaFuncAttributeMaxDynamicSharedMemorySize, smem_flash);
    cudaFuncSetAttribute(out_kernel,
                         cudaFuncAttributeMaxDynamicSharedMemorySize, smem_out);

    dim3 grid(N_ / 64, B_);
    proj_kernel<<<grid, 256, smem_proj>>>(x, wt, bt, wp, bp, wg, bg);
    flash_tc_kernel<<<grid, 128, smem_flash>>>();
    out_kernel<<<grid, 256, smem_out>>>(wo, bo, x, out);
}

// round 3
// speedup vs baseline: 3.4785x; 1.2219x over previous
#include <cuda_runtime.h>

// NonLocalAttention: B=4, C=256, H=W=64 -> N=4096, C8=32, C2=128
//   proj_tc_kernel : theta/phi/g projections, tf32 mma with split-x (2xtf32)
//   flash_tc_kernel: tf32 mma flash attention, unnormalized exp softmax
//   out_tc_kernel  : w_o @ att + b_o + x, tf32 mma with split-att

#define B_ 4
#define C_ 256
#define N_ 4096
#define C8_ 32
#define C2_ 128

__device__ float d_theta[B_ * C8_ * N_];
__device__ float d_phi[B_ * C8_ * N_];
__device__ float d_g[(size_t)B_ * N_ * C2_];
__device__ float d_att[(size_t)B_ * N_ * C2_];

// ---- intrinsics ----
__device__ __forceinline__ unsigned cvt_tf32(float x) {
    unsigned r;
    asm("cvt.rna.tf32.f32 %0, %1;" : "=r"(r) : "f"(x));
    return r;
}
__device__ __forceinline__ float cvt_tf32f(float x) {
    return __uint_as_float(cvt_tf32(x));
}
__device__ __forceinline__ float ex2f(float x) {
    float r;
    asm("ex2.approx.f32 %0, %1;" : "=f"(r) : "f"(x));
    return r;
}
__device__ __forceinline__ void mma_tf32(
    float& c0, float& c1, float& c2, float& c3,
    unsigned a0, unsigned a1, unsigned a2, unsigned a3,
    unsigned b0, unsigned b1) {
    asm("mma.sync.aligned.m16n8k8.row.col.f32.tf32.tf32.f32 "
        "{%0,%1,%2,%3}, {%4,%5,%6,%7}, {%8,%9}, {%0,%1,%2,%3};"
        : "+f"(c0), "+f"(c1), "+f"(c2), "+f"(c3)
        : "r"(a0), "r"(a1), "r"(a2), "r"(a3), "r"(b0), "r"(b1));
}

// ============================================================================
// Kernel 1: projections via tf32 mma, split-x.
// CTA = 256 thr (8 warps: 2M x 4N). CTA tile: M=32 outs, N=256 pixels, K=256.
// Grid.x = 6 Mgroups * 16 Ngroups = 96, grid.y = B.
// ============================================================================
__global__ void __launch_bounds__(256) proj_tc_kernel(
    const float* __restrict__ x,
    const float* __restrict__ wt, const float* __restrict__ bt,
    const float* __restrict__ wp, const float* __restrict__ bp,
    const float* __restrict__ wg, const float* __restrict__ bg) {
    extern __shared__ float sm[];
    float* ws = sm;                 // [32][36]   tf32 weights (k-phase)
    float* xh = sm + 32 * 36;       // [32][264]  x hi
    float* xl = xh + 32 * 264;      // [32][264]  x lo

    const int b  = blockIdx.y;
    const int Mbase = (blockIdx.x >> 4) * 32;
    const int N0    = (blockIdx.x & 15) * 256;
    const int tid  = threadIdx.x;
    const int wid  = tid >> 5, lane = tid & 31;
    const int m0   = (wid >> 2) * 16;
    const int n0w  = (wid & 3) * 64;
    const int qr = lane >> 2, qc = lane & 3;

    float acc[8][4];
#pragma unroll
    for (int nt = 0; nt < 8; nt++)
#pragma unroll
        for (int j = 0; j < 4; j++) acc[nt][j] = 0.f;

    for (int kp = 0; kp < 8; kp++) {
        const int k0 = kp * 32;
        __syncthreads();
        // stage weights [32 o][32 k] -> tf32(rna)
#pragma unroll
        for (int i = 0; i < 4; i++) {
            int idx = i * 256 + tid;           // 0..1023
            int r = idx >> 5, kk = idx & 31;
            int o = Mbase + r;
            const float* src = (o < 32) ? wt + o * C_
                             : (o < 64) ? wp + (o - 32) * C_
                                        : wg + (o - 64) * C_;
            ws[r * 36 + kk] = cvt_tf32f(src[k0 + kk]);
        }
        // stage x [32 c][256 n], split hi/lo
#pragma unroll
        for (int i = 0; i < 8; i++) {
            int idx = i * 256 + tid;           // 0..2047
            int cc = idx >> 6, nn4 = idx & 63;
            float4 v = *(const float4*)(
                x + ((size_t)(b * C_ + k0 + cc)) * N_ + N0 + nn4 * 4);
            float4 h, l;
            h.x = cvt_tf32f(v.x); l.x = v.x - h.x;
            h.y = cvt_tf32f(v.y); l.y = v.y - h.y;
            h.z = cvt_tf32f(v.z); l.z = v.z - h.z;
            h.w = cvt_tf32f(v.w); l.w = v.w - h.w;
            *(float4*)(xh + cc * 264 + nn4 * 4) = h;
            *(float4*)(xl + cc * 264 + nn4 * 4) = l;
        }
        __syncthreads();

#pragma unroll
        for (int ks = 0; ks < 4; ks++) {
            const float* wrow = ws + (m0 + qr) * 36 + ks * 8 + qc;
            unsigned a0 = __float_as_uint(wrow[0]);
            unsigned a1 = __float_as_uint(wrow[8 * 36]);
            unsigned a2 = __float_as_uint(wrow[4]);
            unsigned a3 = __float_as_uint(wrow[8 * 36 + 4]);
            const float* bh = xh + (ks * 8 + qc) * 264 + n0w + qr;
            const float* bl = xl + (ks * 8 + qc) * 264 + n0w + qr;
#pragma unroll
            for (int nt = 0; nt < 8; nt++) {
                unsigned b0 = __float_as_uint(bh[nt * 8]);
                unsigned b1 = __float_as_uint(bh[4 * 264 + nt * 8]);
                mma_tf32(acc[nt][0], acc[nt][1], acc[nt][2], acc[nt][3],
                         a0, a1, a2, a3, b0, b1);
                unsigned l0 = __float_as_uint(bl[nt * 8]);
                unsigned l1 = __float_as_uint(bl[4 * 264 + nt * 8]);
                mma_tf32(acc[nt][0], acc[nt][1], acc[nt][2], acc[nt][3],
                         a0, a1, a2, a3, l0, l1);
            }
        }
    }

    // epilogue: two output rows per thread
#pragma unroll
    for (int rr = 0; rr < 2; rr++) {
        int o = Mbase + m0 + qr + rr * 8;
        if (o < 32) {
            float bias = bt[o];
            float* dst = d_theta + ((size_t)b * C8_ + o) * N_ + N0 + n0w + qc * 2;
#pragma unroll
            for (int nt = 0; nt < 8; nt++)
                *(float2*)(dst + nt * 8) = make_float2(
                    acc[nt][rr * 2] + bias, acc[nt][rr * 2 + 1] + bias);
        } else if (o < 64) {
            float bias = bp[o - 32];
            float* dst = d_phi + ((size_t)b * C8_ + (o - 32)) * N_ + N0 + n0w + qc * 2;
#pragma unroll
            for (int nt = 0; nt < 8; nt++)
                *(float2*)(dst + nt * 8) = make_float2(
                    acc[nt][rr * 2] + bias, acc[nt][rr * 2 + 1] + bias);
        } else {
            int c2 = o - 64;
            float bias = bg[c2];
#pragma unroll
            for (int nt = 0; nt < 8; nt++) {
                int n = N0 + n0w + qc * 2 + nt * 8;
                d_g[((size_t)b * N_ + n) * C2_ + c2]     = acc[nt][rr * 2] + bias;
                d_g[((size_t)b * N_ + n + 1) * C2_ + c2] = acc[nt][rr * 2 + 1] + bias;
            }
        }
    }
}

// ============================================================================
// Kernel 2: tf32 tensor-core flash attention (R2 + rna conversions).
// ============================================================================
__global__ void __launch_bounds__(128, 2) flash_tc_kernel() {
    extern __shared__ float sm[];
    float* phi_s = sm;              // [64][36]  phi[k][c]
    float* g_s   = sm + 64 * 36;    // [64][136] g[k][c2]

    const int b   = blockIdx.y;
    const int q0  = blockIdx.x * 64;
    const int tid = threadIdx.x;
    const int w    = tid >> 5;
    const int lane = tid & 31;
    const int qr = lane >> 2;
    const int qc = lane & 3;
    const int row0 = q0 + w * 16 + qr;

    const float LOG2E = 1.4426950408889634f;
    unsigned at[4][4];
    {
        const float* tp = d_theta + (size_t)b * C8_ * N_;
#pragma unroll
        for (int kc = 0; kc < 4; kc++) {
            int c = kc * 8 + qc;
            at[kc][0] = cvt_tf32(tp[(size_t)c * N_ + row0] * LOG2E);
            at[kc][1] = cvt_tf32(tp[(size_t)c * N_ + row0 + 8] * LOG2E);
            at[kc][2] = cvt_tf32(tp[(size_t)(c + 4) * N_ + row0] * LOG2E);
            at[kc][3] = cvt_tf32(tp[(size_t)(c + 4) * N_ + row0 + 8] * LOG2E);
        }
    }

    float O[16][4];
#pragma unroll
    for (int nt = 0; nt < 16; nt++)
#pragma unroll
        for (int j = 0; j < 4; j++) O[nt][j] = 0.f;
    float l0 = 0.f, l1 = 0.f;

    const int srcA = (lane & ~3) | ((lane & 3) >> 1);
    const int srcB = srcA + 2;
    const bool odd = lane & 1;

    for (int kt = 0; kt < N_; kt += 64) {
        __syncthreads();
#pragma unroll
        for (int it = 0; it < 16; it++) {
            int idx = it * 128 + tid;
            int c = idx >> 6, k = idx & 63;
            phi_s[k * 36 + c] =
                cvt_tf32f(d_phi[((size_t)b * C8_ + c) * N_ + kt + k]);
        }
        {
            const float4* gg = (const float4*)(d_g + ((size_t)b * N_ + kt) * C2_);
#pragma unroll
            for (int it = 0; it < 16; it++) {
                int idx = it * 128 + tid;
                int k = idx >> 5, c4 = idx & 31;
                float4 v = gg[idx];
                v.x = cvt_tf32f(v.x); v.y = cvt_tf32f(v.y);
                v.z = cvt_tf32f(v.z); v.w = cvt_tf32f(v.w);
                *(float4*)(g_s + k * 136 + c4 * 4) = v;
            }
        }
        __syncthreads();

        // GEMM1: S = theta x phi^T
        float s[8][4];
#pragma unroll
        for (int nt = 0; nt < 8; nt++)
#pragma unroll
            for (int j = 0; j < 4; j++) s[nt][j] = 0.f;

#pragma unroll
        for (int kc = 0; kc < 4; kc++) {
            const float* pb = phi_s + qr * 36 + kc * 8 + qc;
#pragma unroll
            for (int nt = 0; nt < 8; nt++) {
                unsigned b0 = __float_as_uint(pb[nt * 8 * 36]);
                unsigned b1 = __float_as_uint(pb[nt * 8 * 36 + 4]);
                mma_tf32(s[nt][0], s[nt][1], s[nt][2], s[nt][3],
                         at[kc][0], at[kc][1], at[kc][2], at[kc][3], b0, b1);
            }
        }

        // exp2 (rna-rounded) + rowsum of the rounded values
        unsigned p[8][4];
#pragma unroll
        for (int nt = 0; nt < 8; nt++) {
            unsigned e0 = cvt_tf32(ex2f(s[nt][0]));
            unsigned e1 = cvt_tf32(ex2f(s[nt][1]));
            unsigned e2 = cvt_tf32(ex2f(s[nt][2]));
            unsigned e3 = cvt_tf32(ex2f(s[nt][3]));
            l0 += __uint_as_float(e0) + __uint_as_float(e1);
            l1 += __uint_as_float(e2) + __uint_as_float(e3);
            p[nt][0] = e0; p[nt][1] = e1; p[nt][2] = e2; p[nt][3] = e3;
        }

        // GEMM2: O += P x g
#pragma unroll
        for (int ks = 0; ks < 8; ks++) {
            unsigned v00 = __shfl_sync(0xffffffffu, p[ks][0], srcA);
            unsigned v01 = __shfl_sync(0xffffffffu, p[ks][1], srcA);
            unsigned v10 = __shfl_sync(0xffffffffu, p[ks][2], srcA);
            unsigned v11 = __shfl_sync(0xffffffffu, p[ks][3], srcA);
            unsigned u00 = __shfl_sync(0xffffffffu, p[ks][0], srcB);
            unsigned u01 = __shfl_sync(0xffffffffu, p[ks][1], srcB);
            unsigned u10 = __shfl_sync(0xffffffffu, p[ks][2], srcB);
            unsigned u11 = __shfl_sync(0xffffffffu, p[ks][3], srcB);
            unsigned a0 = odd ? v01 : v00;
            unsigned a1 = odd ? v11 : v10;
            unsigned a2 = odd ? u01 : u00;
            unsigned a3 = odd ? u11 : u10;

            const float* gb = g_s + (ks * 8 + qc) * 136 + qr;
#pragma unroll
            for (int nt = 0; nt < 16; nt++) {
                unsigned b0 = __float_as_uint(gb[nt * 8]);
                unsigned b1 = __float_as_uint(gb[nt * 8 + 4 * 136]);
                mma_tf32(O[nt][0], O[nt][1], O[nt][2], O[nt][3],
                         a0, a1, a2, a3, b0, b1);
            }
        }
    }

    l0 += __shfl_xor_sync(0xffffffffu, l0, 1);
    l0 += __shfl_xor_sync(0xffffffffu, l0, 2);
    l1 += __shfl_xor_sync(0xffffffffu, l1, 1);
    l1 += __shfl_xor_sync(0xffffffffu, l1, 2);
    float inv0 = 1.0f / l0;
    float inv1 = 1.0f / l1;

    float* dst0 = d_att + ((size_t)b * N_ + row0) * C2_ + qc * 2;
#pragma unroll
    for (int nt = 0; nt < 16; nt++) {
        *(float2*)(dst0 + nt * 8) =
            make_float2(O[nt][0] * inv0, O[nt][1] * inv0);
        *(float2*)(dst0 + 8 * C2_ + nt * 8) =
            make_float2(O[nt][2] * inv1, O[nt][3] * inv1);
    }
}

// ============================================================================
// Kernel 3: out = w_o @ att + b_o + x via tf32 mma, split-att.
// CTA = 256 thr (8 warps: 2M x 4N). CTA tile: M=32 ch, N=128 px, K=128.
// Grid.x = 8 Mgroups * 32 Ngroups = 256, grid.y = B.
// ============================================================================
__global__ void __launch_bounds__(256) out_tc_kernel(
    const float* __restrict__ wo, const float* __restrict__ bo,
    const float* __restrict__ x, float* __restrict__ out) {
    extern __shared__ float sm[];
    float* w_s = sm;                // [32][132]  full-K tf32 weights
    float* ah  = sm + 32 * 132;     // [128][36]  att hi (k-phase)
    float* al  = ah + 128 * 36;     // [128][36]  att lo

    const int b  = blockIdx.y;
    const int Cbase = (blockIdx.x >> 5) * 32;
    const int N0    = (blockIdx.x & 31) * 128;
    const int tid  = threadIdx.x;
    const int wid  = tid >> 5, lane = tid & 31;
    const int m0   = (wid >> 2) * 16;
    const int n0w  = (wid & 3) * 32;
    const int qr = lane >> 2, qc = lane & 3;

    // stage w_o [32 c][128 c2] once
#pragma unroll
    for (int i = 0; i < 16; i++) {
        int idx = i * 256 + tid;          // 0..4095
        int r = idx >> 7, kk = idx & 127;
        w_s[r * 132 + kk] = cvt_tf32f(wo[(Cbase + r) * C2_ + kk]);
    }

    float acc[4][4];
#pragma unroll
    for (int nt = 0; nt < 4; nt++)
#pragma unroll
        for (int j = 0; j < 4; j++) acc[nt][j] = 0.f;

    for (int kp = 0; kp < 4; kp++) {
        const int k0 = kp * 32;
        __syncthreads();
        // stage att [128 n][32 k], split hi/lo
#pragma unroll
        for (int i = 0; i < 4; i++) {
            int idx = i * 256 + tid;      // 0..1023
            int nn = idx >> 3, kk4 = idx & 7;
            float4 v = *(const float4*)(
                d_att + ((size_t)b * N_ + N0 + nn) * C2_ + k0 + kk4 * 4);
            float4 h, l;
            h.x = cvt_tf32f(v.x); l.x = v.x - h.x;
            h.y = cvt_tf32f(v.y); l.y = v.y - h.y;
            h.z = cvt_tf32f(v.z); l.z = v.z - h.z;
            h.w = cvt_tf32f(v.w); l.w = v.w - h.w;
            *(float4*)(ah + nn * 36 + kk4 * 4) = h;
            *(float4*)(al + nn * 36 + kk4 * 4) = l;
        }
        __syncthreads();

#pragma unroll
        for (int ks = 0; ks < 4; ks++) {
            const float* wrow = w_s + (m0 + qr) * 132 + k0 + ks * 8 + qc;
            unsigned a0 = __float_as_uint(wrow[0]);
            unsigned a1 = __float_as_uint(wrow[8 * 132]);
            unsigned a2 = __float_as_uint(wrow[4]);
            unsigned a3 = __float_as_uint(wrow[8 * 132 + 4]);
#pragma unroll
            for (int nt = 0; nt < 4; nt++) {
                const float* bh = ah + (n0w + nt * 8 + qr) * 36 + ks * 8 + qc;
                const float* bl = al + (n0w + nt * 8 + qr) * 36 + ks * 8 + qc;
                unsigned b0 = __float_as_uint(bh[0]);
                unsigned b1 = __float_as_uint(bh[4]);
                mma_tf32(acc[nt][0], acc[nt][1], acc[nt][2], acc[nt][3],
                         a0, a1, a2, a3, b0, b1);
                unsigned c0 = __float_as_uint(bl[0]);
                unsigned c1 = __float_as_uint(bl[4]);
                mma_tf32(acc[nt][0], acc[nt][1], acc[nt][2], acc[nt][3],
                         a0, a1, a2, a3, c0, c1);
            }
        }
    }

    // epilogue: bias + residual
#pragma unroll
    for (int rr = 0; rr < 2; rr++) {
        int c = Cbase + m0 + qr + rr * 8;
        float bias = bo[c];
#pragma unroll
        for (int nt = 0; nt < 4; nt++) {
            int n = N0 + n0w + qc * 2 + nt * 8;
            size_t idx = ((size_t)b * C_ + c) * N_ + n;
            float2 xv = *(const float2*)(x + idx);
            *(float2*)(out + idx) = make_float2(
                acc[nt][rr * 2] + bias + xv.x,
                acc[nt][rr * 2 + 1] + bias + xv.y);
        }
    }
}

// ============================================================================
extern "C" void kernel_launch(void* const* d_in, const int* in_sizes, int n_in,
                              void* d_out, int out_size) {
    (void)in_sizes; (void)n_in; (void)out_size;
    const float* x  = (const float*)d_in[0];
    const float* wt = (const float*)d_in[1];
    const float* bt = (const float*)d_in[2];
    const float* wp = (const float*)d_in[3];
    const float* bp = (const float*)d_in[4];
    const float* wg = (const float*)d_in[5];
    const float* bg = (const float*)d_in[6];
    const float* wo = (const float*)d_in[7];
    const float* bo = (const float*)d_in[8];
    float* out = (float*)d_out;

    const int smem_proj  = (32 * 36 + 2 * 32 * 264) * 4;   // 72192
    const int smem_flash = (64 * 36 + 64 * 136) * 4;        // 44032
    const int smem_out   = (32 * 132 + 2 * 128 * 36) * 4;   // 53760

    cudaFuncSetAttribute(proj_tc_kernel,
                         cudaFuncAttributeMaxDynamicSharedMemorySize, smem_proj);
    cudaFuncSetAttribute(flash_tc_kernel,
                         cudaFuncAttributeMaxDynamicSharedMemorySize, smem_flash);
    cudaFuncSetAttribute(out_tc_kernel,
                         cudaFuncAttributeMaxDynamicSharedMemorySize, smem_out);

    proj_tc_kernel<<<dim3(96, B_), 256, smem_proj>>>(x, wt, bt, wp, bp, wg, bg);
    flash_tc_kernel<<<dim3(N_ / 64, B_), 128, smem_flash>>>();
    out_tc_kernel<<<dim3(256, B_), 256, smem_out>>>(wo, bo, x, out);
}